// round 7
// baseline (speedup 1.0000x reference)
#include <cuda_runtime.h>
#include <cuda_bf16.h>
#include <math_constants.h>
#include <cstdint>

#define N_ROWS 32768
#define D_DIM  256
#define K_CODES 1024
#define MARGIN 6.0e-3f
#define CAP 12

__device__ float  g_a[N_ROWS];
__device__ float  g_b[K_CODES];
__device__ int    g_idx[N_ROWS];
__device__ double g_part[64];
// pre-swizzled bf16 codebook: 16 chunks x 64 codes x 512B (unit-xor swizzled)
__device__ __align__(128) unsigned char g_eb[K_CODES * D_DIM * 2];

__device__ __forceinline__ uint32_t s2u(const void* p) {
    uint32_t a;
    asm("{ .reg .u64 t; cvta.to.shared.u64 t, %1; cvt.u32.u64 %0, t; }" : "=r"(a) : "l"(p));
    return a;
}
__device__ __forceinline__ uint32_t pbf2(float lo, float hi) {
    uint32_t r;
    asm("{.reg .b16 l,h;\n\tcvt.rn.bf16.f32 l,%1;\n\tcvt.rn.bf16.f32 h,%2;\n\tmov.b32 %0,{l,h};}"
        : "=r"(r) : "f"(lo), "f"(hi));
    return r;
}
__device__ __forceinline__ uint32_t fmap(float f) {
    uint32_t b = __float_as_uint(f);
    return b ^ ((b & 0x80000000u) ? 0xFFFFFFFFu : 0x80000000u);
}
__device__ __forceinline__ float funmap(uint32_t u) {
    uint32_t b = (u & 0x80000000u) ? (u ^ 0x80000000u) : ~u;
    return __uint_as_float(b);
}
#define LDSM4(d, addr) \
    asm volatile("ldmatrix.sync.aligned.m8n8.x4.shared.b16 {%0,%1,%2,%3}, [%4];" \
        : "=r"((d)[0]), "=r"((d)[1]), "=r"((d)[2]), "=r"((d)[3]) : "r"(addr))
#define MMA16816(c, a, b0, b1) \
    asm volatile("mma.sync.aligned.m16n8k16.row.col.f32.bf16.bf16.f32 " \
        "{%0,%1,%2,%3}, {%4,%5,%6,%7}, {%8,%9}, {%0,%1,%2,%3};" \
        : "+f"((c)[0]), "+f"((c)[1]), "+f"((c)[2]), "+f"((c)[3]) \
        : "r"((a)[0]), "r"((a)[1]), "r"((a)[2]), "r"((a)[3]), "r"(b0), "r"(b1))
#define MB_INIT(mb, c) \
    asm volatile("mbarrier.init.shared.b64 [%0], %1;" :: "r"((uint32_t)(mb)), "r"((uint32_t)(c)) : "memory")
#define MB_EXPECT(mb, n) \
    asm volatile("mbarrier.arrive.expect_tx.shared.b64 _, [%0], %1;" :: "r"((uint32_t)(mb)), "r"((uint32_t)(n)) : "memory")
#define BULK_G2S(dst, src, n, mb) \
    asm volatile("cp.async.bulk.shared::cluster.global.mbarrier::complete_tx::bytes [%0], [%1], %2, [%3];" \
        :: "r"((uint32_t)(dst)), "l"(src), "r"((uint32_t)(n)), "r"((uint32_t)(mb)) : "memory")
#define MB_WAIT(mb, ph) do { \
    uint32_t _m=(uint32_t)(mb), _p=(uint32_t)(ph), _d; \
    asm volatile("{\n\t.reg .pred p;\n\tmbarrier.try_wait.parity.acquire.cta.shared::cta.b64 p, [%1], %2;\n\tselp.b32 %0, 1, 0, p;\n\t}" : "=r"(_d) : "r"(_m), "r"(_p) : "memory"); \
    if (!_d) { asm volatile("{\n\t.reg .pred P1;\n\tWL_%=:\n\tmbarrier.try_wait.parity.acquire.cta.shared::cta.b64 P1, [%0], %1, 0x989680;\n\t@P1 bra.uni WD_%=;\n\tbra.uni WL_%=;\n\tWD_%=:\n\t}" :: "r"(_m), "r"(_p) : "memory"); } \
} while (0)

// smem layout (bytes)
#define OFF_A     0         // 256 rows x 512B = 131072
#define OFF_B     131072    // 2 bufs x 32KB = 65536
#define OFF_SHB   196608    // float[1024] = 4096
#define OFF_SMIN  200704    // uint[256]
#define OFF_CNT   201728    // int[256]
#define OFF_LIMF  202752    // float[256]
#define OFF_SBEST 203776    // ull[256] = 2048
#define OFF_MBAR  205824    // 2 x 8B, pad
#define OFF_CAND  205952    // ull[256*CAP] = 24576
#define SMEM_SZ   230528

// ===== kernel 1: norms (bitwise identical math) + emb -> pre-swizzled bf16 =====
__global__ void prep_norms(const float* __restrict__ z, const float* __restrict__ emb) {
    int warp = (blockIdx.x * blockDim.x + threadIdx.x) >> 5;
    int lane = threadIdx.x & 31;
    if (blockIdx.x == 0 && threadIdx.x < 64) g_part[threadIdx.x] = 0.0;
    const float* src; float* dst; bool is_e = false; int er = 0;
    if (warp < N_ROWS) { src = z + (size_t)warp * D_DIM; dst = g_a + warp; }
    else if (warp < N_ROWS + K_CODES) { er = warp - N_ROWS; src = emb + (size_t)er * D_DIM; dst = g_b + er; is_e = true; }
    else return;
    const int chunk = er >> 6, r = er & 63;
    const uint32_t ebase = (uint32_t)chunk * 32768u + (uint32_t)r * 512u;
    float s = 0.f;
#pragma unroll
    for (int i = 0; i < D_DIM / 32; i++) {
        float v = src[lane + i * 32];
        s = __fmaf_rn(v, v, s);
        if (is_e) {
            int j = lane + i * 32;
            uint32_t u = (uint32_t)(j >> 3);
            uint32_t off = ebase + (((u ^ (uint32_t)(r & 7)) << 4) | (uint32_t)((j & 7) * 2));
            *reinterpret_cast<__nv_bfloat16*>(g_eb + off) = __float2bfloat16_rn(v);
        }
    }
#pragma unroll
    for (int o = 16; o > 0; o >>= 1) s = __fadd_rn(s, __shfl_down_sync(0xffffffffu, s, o));
    if (lane == 0) *dst = s;
}

// exact fp32 rescore: identical op sequence to the rel_err=0 scalar kernel
__device__ __noinline__ void rescore(const float* __restrict__ z, const float* __restrict__ emb,
                                     int row, int k,
                                     unsigned long long* __restrict__ sbest) {
    const float* zr = z + (size_t)row * D_DIM;
    const float* er = emb + (size_t)k * D_DIM;
    float c = 0.f;
#pragma unroll 8
    for (int i = 0; i < D_DIM; i += 4) {
        float4 a = *reinterpret_cast<const float4*>(zr + i);
        float4 b = *reinterpret_cast<const float4*>(er + i);
        c = __fmaf_rn(a.x, b.x, c); c = __fmaf_rn(a.y, b.y, c);
        c = __fmaf_rn(a.z, b.z, c); c = __fmaf_rn(a.w, b.w, c);
    }
    float d = __fmaf_rn(-2.0f, c, __fadd_rn(g_a[row], g_b[k]));
    unsigned long long pk = ((unsigned long long)fmap(d) << 32) | (unsigned)k;
    atomicMin(sbest, pk);
}

__global__ void dummy_k() {}

// ===== kernel 2: single-pass bf16 mma.sync GEMM, 16 warps, 1 wave =====
__global__ __launch_bounds__(512, 1)
void gemm_mma(const float* __restrict__ z, const float* __restrict__ emb) {
    extern __shared__ __align__(128) char smem[];
    const uint32_t sbase = s2u(smem);
    const int tid = threadIdx.x;
    const int t = tid & 31;
    const int w = tid >> 5;
    const int warpm = w & 7;          // 8 m-warps: 32 rows each
    const int warpn = w >> 3;         // 2 n-warps: 32 codes each
    const int row0 = blockIdx.x * 256;

    float*    shb  = reinterpret_cast<float*>(smem + OFF_SHB);
    uint32_t* smin = reinterpret_cast<uint32_t*>(smem + OFF_SMIN);
    int*      cnt  = reinterpret_cast<int*>(smem + OFF_CNT);
    float*    limf = reinterpret_cast<float*>(smem + OFF_LIMF);
    unsigned long long* sbest = reinterpret_cast<unsigned long long*>(smem + OFF_SBEST);
    unsigned long long* cand  = reinterpret_cast<unsigned long long*>(smem + OFF_CAND);
    const uint32_t mbar0 = sbase + OFF_MBAR, mbar1 = sbase + OFF_MBAR + 8;

    if (tid < 256) { smin[tid] = 0xFF800000u; cnt[tid] = 0; sbest[tid] = ~0ull; }
    for (int i = tid; i < K_CODES; i += 512) shb[i] = g_b[i];
    if (tid == 0) { MB_INIT(mbar0, 1); MB_INIT(mbar1, 1); }
    __syncthreads();

    // kick off B chunks 0 and 1 (g_eb is pre-swizzled, 32KB per chunk)
    if (tid == 0) {
        MB_EXPECT(mbar0, 32768);
        BULK_G2S(sbase + OFF_B, (const void*)(g_eb), 32768, mbar0);
        MB_EXPECT(mbar1, 32768);
        BULK_G2S(sbase + OFF_B + 32768, (const void*)(g_eb + 32768), 32768, mbar1);
    }

    // A: 256 rows x 256 bf16 (fp32 -> bf16), 512B pitch, unit-xor swizzle
    for (int i = tid; i < 256 * 32; i += 512) {
        int r = i >> 5, u = i & 31;
        const float4* s4 = reinterpret_cast<const float4*>(z + (size_t)(row0 + r) * D_DIM + u * 8);
        float4 f0 = s4[0], f1 = s4[1];
        uint4 v = { pbf2(f0.x, f0.y), pbf2(f0.z, f0.w), pbf2(f1.x, f1.y), pbf2(f1.z, f1.w) };
        *reinterpret_cast<uint4*>(smem + OFF_A + r * 512 + ((u ^ (r & 7)) << 4)) = v;
    }
    __syncthreads();

    // ldmatrix lane addressing
    const int t7 = t & 7;
    const int arow = t7 + ((t >> 3) & 1) * 8;
    const int asel = (t >> 4) & 1;
    const int brow = t7 + ((t >> 4) & 1) * 8;
    const int bsel = (t >> 3) & 1;
    const uint32_t abase = sbase + OFF_A + (uint32_t)(warpm * 32 + arow) * 512;
    const int n0 = warpn * 32;
    const int crow = t >> 2;
    const int ccol = 2 * (t & 3);

    for (int c = 0; c < 16; c++) {
        const int b = c & 1;
        const int c0 = c * 64;
        const uint32_t mb = b ? mbar1 : mbar0;
        const uint32_t bbase = sbase + OFF_B + (uint32_t)(b * 32768 + (warpn * 32 + brow) * 512);

        MB_WAIT(mb, (c >> 1) & 1);

        float acc[2][4][4];
#pragma unroll
        for (int im = 0; im < 2; im++)
#pragma unroll
            for (int in = 0; in < 4; in++)
#pragma unroll
                for (int r = 0; r < 4; r++) acc[im][in][r] = 0.f;

        uint32_t af[2][2][4], bfr[2][2][4];
        {
            uint32_t ua = (uint32_t)((asel ^ t7) << 4);
            uint32_t ub = (uint32_t)((bsel ^ t7) << 4);
            LDSM4(af[0][0], abase + ua);
            LDSM4(af[0][1], abase + 8192 + ua);
            LDSM4(bfr[0][0], bbase + ub);
            LDSM4(bfr[0][1], bbase + 8192 + ub);
        }
#pragma unroll
        for (int ks = 0; ks < 16; ks++) {
            const int cur = ks & 1, nxt = cur ^ 1;
            if (ks < 15) {
                uint32_t ua = (uint32_t)(((2 * (ks + 1) + asel) ^ t7) << 4);
                uint32_t ub = (uint32_t)(((2 * (ks + 1) + bsel) ^ t7) << 4);
                LDSM4(af[nxt][0], abase + ua);
                LDSM4(af[nxt][1], abase + 8192 + ua);
                LDSM4(bfr[nxt][0], bbase + ub);
                LDSM4(bfr[nxt][1], bbase + 8192 + ub);
            }
#pragma unroll
            for (int im = 0; im < 2; im++) {
                MMA16816(acc[im][0], af[cur][im], bfr[cur][0][0], bfr[cur][0][1]);
                MMA16816(acc[im][1], af[cur][im], bfr[cur][0][2], bfr[cur][0][3]);
                MMA16816(acc[im][2], af[cur][im], bfr[cur][1][0], bfr[cur][1][1]);
                MMA16816(acc[im][3], af[cur][im], bfr[cur][1][2], bfr[cur][1][3]);
            }
        }

        // ---- epilogue: running min + candidate collection ----
#pragma unroll
        for (int im = 0; im < 2; im++) {
#pragma unroll
            for (int h = 0; h < 2; h++) {
                const int row = warpm * 32 + im * 16 + crow + h * 8;
                float se[8];
                float mn = CUDART_INF_F;
#pragma unroll
                for (int in = 0; in < 4; in++) {
                    int nl = n0 + in * 8 + ccol;
                    float s0 = __fmaf_rn(-2.0f, acc[im][in][2 * h],     shb[c0 + nl]);
                    float s1 = __fmaf_rn(-2.0f, acc[im][in][2 * h + 1], shb[c0 + nl + 1]);
                    se[2 * in] = s0; se[2 * in + 1] = s1;
                    mn = fminf(mn, fminf(s0, s1));
                }
                mn = fminf(mn, __shfl_xor_sync(0xffffffffu, mn, 1));
                mn = fminf(mn, __shfl_xor_sync(0xffffffffu, mn, 2));
                if ((t & 3) == 0) atomicMin(&smin[row], fmap(mn));
                float lim = fminf(funmap(smin[row]), mn) + MARGIN;
#pragma unroll
                for (int e = 0; e < 8; e++) {
                    if (se[e] <= lim) {
                        int k = c0 + n0 + (e >> 1) * 8 + ccol + (e & 1);
                        int idx = atomicAdd(&cnt[row], 1);
                        if (idx < CAP)
                            cand[row * CAP + idx] =
                                ((unsigned long long)__float_as_uint(se[e]) << 32) | (unsigned)k;
                    }
                }
            }
        }
        __syncthreads();

        // issue bulk copy for chunk c+2 into the buffer just freed
        if (c < 14 && tid == 0) {
            MB_EXPECT(mb, 32768);
            BULK_G2S(sbase + OFF_B + b * 32768,
                     (const void*)(g_eb + (size_t)(c + 2) * 32768), 32768, mb);
        }
    }

    // ---- final limits, filter, exact rescore ----
    if (tid < 256) limf[tid] = funmap(smin[tid]) + MARGIN;
    __syncthreads();

    for (int i = tid; i < 256 * CAP; i += 512) {
        int row = i / CAP, slot = i % CAP;
        int ne = min(cnt[row], CAP);
        if (slot < ne) {
            unsigned long long pk = cand[row * CAP + slot];
            float s = __uint_as_float((uint32_t)(pk >> 32));
            if (s <= limf[row])
                rescore(z, emb, row0 + row, (int)(unsigned)(pk & 0xFFFFFFFFull), &sbest[row]);
        }
    }
    for (int row = w; row < 256; row += 16) {        // overflow fallback (rare)
        if (cnt[row] > CAP)
            for (int k = t; k < K_CODES; k += 32)
                rescore(z, emb, row0 + row, k, &sbest[row]);
    }
    __syncthreads();

    if (tid < 256) g_idx[row0 + tid] = (int)(unsigned)(sbest[tid] & 0xFFFFFFFFull);
}

// ===== kernel 3: gather + straight-through output + MSE partials =====
__global__ void finalize_out(const float* __restrict__ z, const float* __restrict__ emb,
                             float* __restrict__ out) {
    int tt = blockIdx.x * 256 + threadIdx.x;
    int base = tt * 4, n = base >> 8, d0 = base & 255;
    int code = g_idx[n];
    float4 q  = *reinterpret_cast<const float4*>(&emb[(size_t)code * D_DIM + d0]);
    float4 zv = *reinterpret_cast<const float4*>(&z[(size_t)base]);
    float dx = __fadd_rn(q.x, -zv.x), dy = __fadd_rn(q.y, -zv.y);
    float dz = __fadd_rn(q.z, -zv.z), dw = __fadd_rn(q.w, -zv.w);
    float4 ov = { __fadd_rn(zv.x, dx), __fadd_rn(zv.y, dy), __fadd_rn(zv.z, dz), __fadd_rn(zv.w, dw) };
    *reinterpret_cast<float4*>(&out[(size_t)base]) = ov;

    double s = (double)dx * dx + (double)dy * dy + (double)dz * dz + (double)dw * dw;
#pragma unroll
    for (int o = 16; o > 0; o >>= 1) s += __shfl_down_sync(0xffffffffu, s, o);
    __shared__ double ws[8];
    int lane = threadIdx.x & 31, wid = threadIdx.x >> 5;
    if (lane == 0) ws[wid] = s;
    __syncthreads();
    if (threadIdx.x == 0) {
        double bs = 0.0;
#pragma unroll
        for (int ww = 0; ww < 8; ww++) bs += ws[ww];
        atomicAdd(&g_part[blockIdx.x & 63], bs);
    }
}

__global__ void loss_final(float* __restrict__ out, int out_size) {
    if (threadIdx.x == 0 && blockIdx.x == 0) {
        double s = 0.0;
        for (int i = 0; i < 64; i++) s += g_part[i];
        float mf = (float)(s / (double)((size_t)N_ROWS * D_DIM));
        out[out_size - 1] = __fadd_rn(mf, __fmul_rn(0.25f, mf));
    }
}

extern "C" void kernel_launch(void* const* d_in, const int* in_sizes, int n_in,
                              void* d_out, int out_size) {
    const float* z   = (const float*)d_in[0];
    const float* emb = (const float*)d_in[1];
    float* out = (float*)d_out;

    cudaFuncSetAttribute(gemm_mma, cudaFuncAttributeMaxDynamicSharedMemorySize, SMEM_SZ);

    prep_norms<<<(N_ROWS + K_CODES) / 8, 256>>>(z, emb);
    dummy_k<<<1, 32>>>();      // launch-index padding so ncu (-s 5 -c 1)
    dummy_k<<<1, 32>>>();      // lands on gemm_mma
    gemm_mma<<<N_ROWS / 256, 512, SMEM_SZ>>>(z, emb);
    finalize_out<<<(N_ROWS * D_DIM) / (256 * 4), 256>>>(z, emb, out);
    loss_final<<<1, 32>>>(out, out_size);
}

// round 8
// speedup vs baseline: 1.4029x; 1.4029x over previous
#include <cuda_runtime.h>
#include <cuda_bf16.h>
#include <math_constants.h>
#include <cstdint>

#define N_ROWS 32768
#define D_DIM  256
#define K_CODES 1024
#define MARGIN 6.0e-3f
#define CAP 12

__device__ float  g_a[N_ROWS];
__device__ float  g_b[K_CODES];
__device__ int    g_idx[N_ROWS];
__device__ double g_part[64];
// pre-swizzled bf16 codebook: 16 chunks x 64 codes x 512B (unit-xor swizzled)
__device__ __align__(128) unsigned char g_eb[K_CODES * D_DIM * 2];

__device__ __forceinline__ uint32_t s2u(const void* p) {
    uint32_t a;
    asm("{ .reg .u64 t; cvta.to.shared.u64 t, %1; cvt.u32.u64 %0, t; }" : "=r"(a) : "l"(p));
    return a;
}
__device__ __forceinline__ uint32_t pbf2(float lo, float hi) {
    uint32_t r;
    asm("{.reg .b16 l,h;\n\tcvt.rn.bf16.f32 l,%1;\n\tcvt.rn.bf16.f32 h,%2;\n\tmov.b32 %0,{l,h};}"
        : "=r"(r) : "f"(lo), "f"(hi));
    return r;
}
__device__ __forceinline__ uint32_t fmap(float f) {
    uint32_t b = __float_as_uint(f);
    return b ^ ((b & 0x80000000u) ? 0xFFFFFFFFu : 0x80000000u);
}
__device__ __forceinline__ float funmap(uint32_t u) {
    uint32_t b = (u & 0x80000000u) ? (u ^ 0x80000000u) : ~u;
    return __uint_as_float(b);
}
#define LDSM4(d, addr) \
    asm volatile("ldmatrix.sync.aligned.m8n8.x4.shared.b16 {%0,%1,%2,%3}, [%4];" \
        : "=r"((d)[0]), "=r"((d)[1]), "=r"((d)[2]), "=r"((d)[3]) : "r"(addr))
#define MMA16816(c, a, b0, b1) \
    asm volatile("mma.sync.aligned.m16n8k16.row.col.f32.bf16.bf16.f32 " \
        "{%0,%1,%2,%3}, {%4,%5,%6,%7}, {%8,%9}, {%0,%1,%2,%3};" \
        : "+f"((c)[0]), "+f"((c)[1]), "+f"((c)[2]), "+f"((c)[3]) \
        : "r"((a)[0]), "r"((a)[1]), "r"((a)[2]), "r"((a)[3]), "r"(b0), "r"(b1))
#define MB_INIT(mb, c) \
    asm volatile("mbarrier.init.shared.b64 [%0], %1;" :: "r"((uint32_t)(mb)), "r"((uint32_t)(c)) : "memory")
#define MB_EXPECT(mb, n) \
    asm volatile("mbarrier.arrive.expect_tx.shared.b64 _, [%0], %1;" :: "r"((uint32_t)(mb)), "r"((uint32_t)(n)) : "memory")
#define BULK_G2S(dst, src, n, mb) \
    asm volatile("cp.async.bulk.shared::cluster.global.mbarrier::complete_tx::bytes [%0], [%1], %2, [%3];" \
        :: "r"((uint32_t)(dst)), "l"(src), "r"((uint32_t)(n)), "r"((uint32_t)(mb)) : "memory")
#define MB_WAIT(mb, ph) do { \
    uint32_t _m=(uint32_t)(mb), _p=(uint32_t)(ph), _d; \
    asm volatile("{\n\t.reg .pred p;\n\tmbarrier.try_wait.parity.acquire.cta.shared::cta.b64 p, [%1], %2;\n\tselp.b32 %0, 1, 0, p;\n\t}" : "=r"(_d) : "r"(_m), "r"(_p) : "memory"); \
    if (!_d) { asm volatile("{\n\t.reg .pred P1;\n\tWL_%=:\n\tmbarrier.try_wait.parity.acquire.cta.shared::cta.b64 P1, [%0], %1, 0x989680;\n\t@P1 bra.uni WD_%=;\n\tbra.uni WL_%=;\n\tWD_%=:\n\t}" :: "r"(_m), "r"(_p) : "memory"); } \
} while (0)

// smem layout (bytes)
#define OFF_A     0         // 256 rows x 512B = 131072
#define OFF_B     131072    // 2 bufs x 32KB = 65536
#define OFF_SHB   196608    // float[1024] = 4096
#define OFF_SMIN  200704    // uint[256]
#define OFF_CNT   201728    // int[256]
#define OFF_LIMF  202752    // float[256]
#define OFF_SBEST 203776    // ull[256] = 2048
#define OFF_MBAR  205824    // 2 x 8B, pad
#define OFF_CAND  205952    // ull[256*CAP] = 24576
#define SMEM_SZ   230528

// ===== kernel 1: norms (bitwise identical math) + emb -> pre-swizzled bf16 =====
__global__ void prep_norms(const float* __restrict__ z, const float* __restrict__ emb) {
    int warp = (blockIdx.x * blockDim.x + threadIdx.x) >> 5;
    int lane = threadIdx.x & 31;
    if (blockIdx.x == 0 && threadIdx.x < 64) g_part[threadIdx.x] = 0.0;
    const float* src; float* dst; bool is_e = false; int er = 0;
    if (warp < N_ROWS) { src = z + (size_t)warp * D_DIM; dst = g_a + warp; }
    else if (warp < N_ROWS + K_CODES) { er = warp - N_ROWS; src = emb + (size_t)er * D_DIM; dst = g_b + er; is_e = true; }
    else return;
    const int chunk = er >> 6, r = er & 63;
    const uint32_t ebase = (uint32_t)chunk * 32768u + (uint32_t)r * 512u;
    float s = 0.f;
#pragma unroll
    for (int i = 0; i < D_DIM / 32; i++) {
        float v = src[lane + i * 32];
        s = __fmaf_rn(v, v, s);
        if (is_e) {
            int j = lane + i * 32;
            uint32_t u = (uint32_t)(j >> 3);
            uint32_t off = ebase + (((u ^ (uint32_t)(r & 7)) << 4) | (uint32_t)((j & 7) * 2));
            *reinterpret_cast<__nv_bfloat16*>(g_eb + off) = __float2bfloat16_rn(v);
        }
    }
#pragma unroll
    for (int o = 16; o > 0; o >>= 1) s = __fadd_rn(s, __shfl_down_sync(0xffffffffu, s, o));
    if (lane == 0) *dst = s;
}

// exact fp32 rescore: identical op sequence to the rel_err=0 scalar kernel
__device__ __noinline__ void rescore(const float* __restrict__ z, const float* __restrict__ emb,
                                     int row, int k,
                                     unsigned long long* __restrict__ sbest) {
    const float* zr = z + (size_t)row * D_DIM;
    const float* er = emb + (size_t)k * D_DIM;
    float c = 0.f;
#pragma unroll 8
    for (int i = 0; i < D_DIM; i += 4) {
        float4 a = *reinterpret_cast<const float4*>(zr + i);
        float4 b = *reinterpret_cast<const float4*>(er + i);
        c = __fmaf_rn(a.x, b.x, c); c = __fmaf_rn(a.y, b.y, c);
        c = __fmaf_rn(a.z, b.z, c); c = __fmaf_rn(a.w, b.w, c);
    }
    float d = __fmaf_rn(-2.0f, c, __fadd_rn(g_a[row], g_b[k]));
    unsigned long long pk = ((unsigned long long)fmap(d) << 32) | (unsigned)k;
    atomicMin(sbest, pk);
}

__global__ void dummy_k() {}

// ===== kernel 2: single-pass bf16 mma.sync GEMM, 16 warps, 1 wave, no spills =====
__global__ __launch_bounds__(512, 1)
void gemm_mma(const float* __restrict__ z, const float* __restrict__ emb) {
    extern __shared__ __align__(128) char smem[];
    const uint32_t sbase = s2u(smem);
    const int tid = threadIdx.x;
    const int t = tid & 31;
    const int w = tid >> 5;
    const int warpm = w & 7;          // 8 m-warps: 32 rows each
    const int warpn = w >> 3;         // 2 n-warps: 32 codes each
    const int row0 = blockIdx.x * 256;

    float*    shb  = reinterpret_cast<float*>(smem + OFF_SHB);
    uint32_t* smin = reinterpret_cast<uint32_t*>(smem + OFF_SMIN);
    int*      cnt  = reinterpret_cast<int*>(smem + OFF_CNT);
    float*    limf = reinterpret_cast<float*>(smem + OFF_LIMF);
    unsigned long long* sbest = reinterpret_cast<unsigned long long*>(smem + OFF_SBEST);
    unsigned long long* cand  = reinterpret_cast<unsigned long long*>(smem + OFF_CAND);
    const uint32_t mbar0 = sbase + OFF_MBAR, mbar1 = sbase + OFF_MBAR + 8;

    if (tid < 256) { smin[tid] = 0xFF800000u; cnt[tid] = 0; sbest[tid] = ~0ull; }
    for (int i = tid; i < K_CODES; i += 512) shb[i] = g_b[i];
    if (tid == 0) { MB_INIT(mbar0, 1); MB_INIT(mbar1, 1); }
    __syncthreads();

    // kick off B chunks 0 and 1 (g_eb is pre-swizzled, 32KB per chunk)
    if (tid == 0) {
        MB_EXPECT(mbar0, 32768);
        BULK_G2S(sbase + OFF_B, (const void*)(g_eb), 32768, mbar0);
        MB_EXPECT(mbar1, 32768);
        BULK_G2S(sbase + OFF_B + 32768, (const void*)(g_eb + 32768), 32768, mbar1);
    }

    // A: 256 rows x 256 bf16 (fp32 -> bf16), 512B pitch, unit-xor swizzle
    for (int i = tid; i < 256 * 32; i += 512) {
        int r = i >> 5, u = i & 31;
        const float4* s4 = reinterpret_cast<const float4*>(z + (size_t)(row0 + r) * D_DIM + u * 8);
        float4 f0 = s4[0], f1 = s4[1];
        uint4 v = { pbf2(f0.x, f0.y), pbf2(f0.z, f0.w), pbf2(f1.x, f1.y), pbf2(f1.z, f1.w) };
        *reinterpret_cast<uint4*>(smem + OFF_A + r * 512 + ((u ^ (r & 7)) << 4)) = v;
    }
    __syncthreads();

    // ldmatrix lane addressing
    const int t7 = t & 7;
    const int arow = t7 + ((t >> 3) & 1) * 8;
    const int asel = (t >> 4) & 1;
    const int brow = t7 + ((t >> 4) & 1) * 8;
    const int bsel = (t >> 3) & 1;
    const uint32_t abase = sbase + OFF_A + (uint32_t)(warpm * 32 + arow) * 512;
    const int n0 = warpn * 32;
    const int crow = t >> 2;
    const int ccol = 2 * (t & 3);

    for (int c = 0; c < 16; c++) {
        const int b = c & 1;
        const int c0 = c * 64;
        const uint32_t mb = b ? mbar1 : mbar0;
        const uint32_t bbase = sbase + OFF_B + (uint32_t)(b * 32768 + (warpn * 32 + brow) * 512);

        MB_WAIT(mb, (c >> 1) & 1);

        float acc[2][4][4];
#pragma unroll
        for (int im = 0; im < 2; im++)
#pragma unroll
            for (int in = 0; in < 4; in++)
#pragma unroll
                for (int r = 0; r < 4; r++) acc[im][in][r] = 0.f;

        // single-buffered fragments: fewer live regs, warp-level parallelism
        // (4 warps/SMSP) hides the LDSM->MMA dependency.
#pragma unroll
        for (int ks = 0; ks < 16; ks++) {
            uint32_t ua = (uint32_t)(((2 * ks + asel) ^ t7) << 4);
            uint32_t ub = (uint32_t)(((2 * ks + bsel) ^ t7) << 4);
            uint32_t af[2][4], bf[2][4];
            LDSM4(af[0], abase + ua);
            LDSM4(af[1], abase + 8192 + ua);
            LDSM4(bf[0], bbase + ub);
            LDSM4(bf[1], bbase + 8192 + ub);
#pragma unroll
            for (int im = 0; im < 2; im++) {
                MMA16816(acc[im][0], af[im], bf[0][0], bf[0][1]);
                MMA16816(acc[im][1], af[im], bf[0][2], bf[0][3]);
                MMA16816(acc[im][2], af[im], bf[1][0], bf[1][1]);
                MMA16816(acc[im][3], af[im], bf[1][2], bf[1][3]);
            }
        }

        // ---- epilogue phase 1: per-row running min ----
#pragma unroll
        for (int im = 0; im < 2; im++) {
#pragma unroll
            for (int h = 0; h < 2; h++) {
                const int row = warpm * 32 + im * 16 + crow + h * 8;
                float mn = CUDART_INF_F;
#pragma unroll
                for (int in = 0; in < 4; in++) {
                    int nl = n0 + in * 8 + ccol;
                    mn = fminf(mn, __fmaf_rn(-2.0f, acc[im][in][2 * h],     shb[c0 + nl]));
                    mn = fminf(mn, __fmaf_rn(-2.0f, acc[im][in][2 * h + 1], shb[c0 + nl + 1]));
                }
                mn = fminf(mn, __shfl_xor_sync(0xffffffffu, mn, 1));
                mn = fminf(mn, __shfl_xor_sync(0xffffffffu, mn, 2));
                if ((t & 3) == 0) atomicMin(&smin[row], fmap(mn));
            }
        }
        __syncthreads();   // smin now holds the true running min incl. this chunk

        // ---- epilogue phase 2: tight-limit candidate collection ----
#pragma unroll
        for (int im = 0; im < 2; im++) {
#pragma unroll
            for (int h = 0; h < 2; h++) {
                const int row = warpm * 32 + im * 16 + crow + h * 8;
                const float lim = funmap(smin[row]) + MARGIN;
#pragma unroll
                for (int in = 0; in < 4; in++) {
#pragma unroll
                    for (int p = 0; p < 2; p++) {
                        int nl = n0 + in * 8 + ccol + p;
                        float s = __fmaf_rn(-2.0f, acc[im][in][2 * h + p], shb[c0 + nl]);
                        if (s <= lim) {
                            int idx = atomicAdd(&cnt[row], 1);
                            if (idx < CAP)
                                cand[row * CAP + idx] =
                                    ((unsigned long long)__float_as_uint(s) << 32) | (unsigned)(c0 + nl);
                        }
                    }
                }
            }
        }
        __syncthreads();

        // issue bulk copy for chunk c+2 into the buffer just freed
        if (c < 14 && tid == 0) {
            MB_EXPECT(mb, 32768);
            BULK_G2S(sbase + OFF_B + b * 32768,
                     (const void*)(g_eb + (size_t)(c + 2) * 32768), 32768, mb);
        }
    }

    // ---- final limits, filter, exact rescore ----
    if (tid < 256) limf[tid] = funmap(smin[tid]) + MARGIN;
    __syncthreads();

    for (int i = tid; i < 256 * CAP; i += 512) {
        int row = i / CAP, slot = i % CAP;
        int ne = min(cnt[row], CAP);
        if (slot < ne) {
            unsigned long long pk = cand[row * CAP + slot];
            float s = __uint_as_float((uint32_t)(pk >> 32));
            if (s <= limf[row])
                rescore(z, emb, row0 + row, (int)(unsigned)(pk & 0xFFFFFFFFull), &sbest[row]);
        }
    }
    for (int row = w; row < 256; row += 16) {        // overflow fallback (rare now)
        if (cnt[row] > CAP)
            for (int k = t; k < K_CODES; k += 32)
                rescore(z, emb, row0 + row, k, &sbest[row]);
    }
    __syncthreads();

    if (tid < 256) g_idx[row0 + tid] = (int)(unsigned)(sbest[tid] & 0xFFFFFFFFull);
}

// ===== kernel 3: gather + straight-through output + MSE partials =====
__global__ void finalize_out(const float* __restrict__ z, const float* __restrict__ emb,
                             float* __restrict__ out) {
    int tt = blockIdx.x * 256 + threadIdx.x;
    int base = tt * 4, n = base >> 8, d0 = base & 255;
    int code = g_idx[n];
    float4 q  = *reinterpret_cast<const float4*>(&emb[(size_t)code * D_DIM + d0]);
    float4 zv = *reinterpret_cast<const float4*>(&z[(size_t)base]);
    float dx = __fadd_rn(q.x, -zv.x), dy = __fadd_rn(q.y, -zv.y);
    float dz = __fadd_rn(q.z, -zv.z), dw = __fadd_rn(q.w, -zv.w);
    float4 ov = { __fadd_rn(zv.x, dx), __fadd_rn(zv.y, dy), __fadd_rn(zv.z, dz), __fadd_rn(zv.w, dw) };
    *reinterpret_cast<float4*>(&out[(size_t)base]) = ov;

    double s = (double)dx * dx + (double)dy * dy + (double)dz * dz + (double)dw * dw;
#pragma unroll
    for (int o = 16; o > 0; o >>= 1) s += __shfl_down_sync(0xffffffffu, s, o);
    __shared__ double ws[8];
    int lane = threadIdx.x & 31, wid = threadIdx.x >> 5;
    if (lane == 0) ws[wid] = s;
    __syncthreads();
    if (threadIdx.x == 0) {
        double bs = 0.0;
#pragma unroll
        for (int ww = 0; ww < 8; ww++) bs += ws[ww];
        atomicAdd(&g_part[blockIdx.x & 63], bs);
    }
}

__global__ void loss_final(float* __restrict__ out, int out_size) {
    if (threadIdx.x == 0 && blockIdx.x == 0) {
        double s = 0.0;
        for (int i = 0; i < 64; i++) s += g_part[i];
        float mf = (float)(s / (double)((size_t)N_ROWS * D_DIM));
        out[out_size - 1] = __fadd_rn(mf, __fmul_rn(0.25f, mf));
    }
}

extern "C" void kernel_launch(void* const* d_in, const int* in_sizes, int n_in,
                              void* d_out, int out_size) {
    const float* z   = (const float*)d_in[0];
    const float* emb = (const float*)d_in[1];
    float* out = (float*)d_out;

    cudaFuncSetAttribute(gemm_mma, cudaFuncAttributeMaxDynamicSharedMemorySize, SMEM_SZ);

    prep_norms<<<(N_ROWS + K_CODES) / 8, 256>>>(z, emb);
    dummy_k<<<1, 32>>>();      // launch-index padding so ncu (-s 5 -c 1)
    dummy_k<<<1, 32>>>();      // lands on gemm_mma
    gemm_mma<<<N_ROWS / 256, 512, SMEM_SZ>>>(z, emb);
    finalize_out<<<(N_ROWS * D_DIM) / (256 * 4), 256>>>(z, emb, out);
    loss_final<<<1, 32>>>(out, out_size);
}

// round 9
// speedup vs baseline: 15.6446x; 11.1514x over previous
#include <cuda_runtime.h>
#include <cuda_bf16.h>
#include <math_constants.h>
#include <cstdint>

#define N_ROWS 32768
#define D_DIM  256
#define K_CODES 1024
#define MARGIN 3.0e-3f
#define CAP 24

__device__ float  g_a[N_ROWS];
__device__ float  g_b[K_CODES];
__device__ int    g_idx[N_ROWS];
__device__ double g_part[64];
// pre-swizzled bf16 codebook: 16 chunks x 64 codes x 512B (unit-xor swizzled)
__device__ __align__(128) unsigned char g_eb[K_CODES * D_DIM * 2];

__device__ __forceinline__ uint32_t s2u(const void* p) {
    uint32_t a;
    asm("{ .reg .u64 t; cvta.to.shared.u64 t, %1; cvt.u32.u64 %0, t; }" : "=r"(a) : "l"(p));
    return a;
}
__device__ __forceinline__ uint32_t pbf2(float lo, float hi) {
    uint32_t r;
    asm("{.reg .b16 l,h;\n\tcvt.rn.bf16.f32 l,%1;\n\tcvt.rn.bf16.f32 h,%2;\n\tmov.b32 %0,{l,h};}"
        : "=r"(r) : "f"(lo), "f"(hi));
    return r;
}
__device__ __forceinline__ uint32_t fmap(float f) {
    uint32_t b = __float_as_uint(f);
    return b ^ ((b & 0x80000000u) ? 0xFFFFFFFFu : 0x80000000u);
}
__device__ __forceinline__ float funmap(uint32_t u) {
    uint32_t b = (u & 0x80000000u) ? (u ^ 0x80000000u) : ~u;
    return __uint_as_float(b);
}
#define LDSM4(d, addr) \
    asm volatile("ldmatrix.sync.aligned.m8n8.x4.shared.b16 {%0,%1,%2,%3}, [%4];" \
        : "=r"((d)[0]), "=r"((d)[1]), "=r"((d)[2]), "=r"((d)[3]) : "r"(addr))
#define MMA16816(c, a, b0, b1) \
    asm volatile("mma.sync.aligned.m16n8k16.row.col.f32.bf16.bf16.f32 " \
        "{%0,%1,%2,%3}, {%4,%5,%6,%7}, {%8,%9}, {%0,%1,%2,%3};" \
        : "+f"((c)[0]), "+f"((c)[1]), "+f"((c)[2]), "+f"((c)[3]) \
        : "r"((a)[0]), "r"((a)[1]), "r"((a)[2]), "r"((a)[3]), "r"(b0), "r"(b1))
#define MB_INIT(mb, c) \
    asm volatile("mbarrier.init.shared.b64 [%0], %1;" :: "r"((uint32_t)(mb)), "r"((uint32_t)(c)) : "memory")
#define MB_EXPECT(mb, n) \
    asm volatile("mbarrier.arrive.expect_tx.shared.b64 _, [%0], %1;" :: "r"((uint32_t)(mb)), "r"((uint32_t)(n)) : "memory")
#define BULK_G2S(dst, src, n, mb) \
    asm volatile("cp.async.bulk.shared::cluster.global.mbarrier::complete_tx::bytes [%0], [%1], %2, [%3];" \
        :: "r"((uint32_t)(dst)), "l"(src), "r"((uint32_t)(n)), "r"((uint32_t)(mb)) : "memory")
#define MB_WAIT(mb, ph) do { \
    uint32_t _m=(uint32_t)(mb), _p=(uint32_t)(ph), _d; \
    asm volatile("{\n\t.reg .pred p;\n\tmbarrier.try_wait.parity.acquire.cta.shared::cta.b64 p, [%1], %2;\n\tselp.b32 %0, 1, 0, p;\n\t}" : "=r"(_d) : "r"(_m), "r"(_p) : "memory"); \
    if (!_d) { asm volatile("{\n\t.reg .pred P1;\n\tWL_%=:\n\tmbarrier.try_wait.parity.acquire.cta.shared::cta.b64 P1, [%0], %1, 0x989680;\n\t@P1 bra.uni WD_%=;\n\tbra.uni WL_%=;\n\tWD_%=:\n\t}" :: "r"(_m), "r"(_p) : "memory"); } \
} while (0)

// smem layout (bytes)
#define OFF_A     0         // 256 rows x 512B = 131072
#define OFF_B     131072    // 2 bufs x 32KB = 65536
#define OFF_SHB   196608    // float[1024] = 4096
#define OFF_SMIN  200704    // uint[256]
#define OFF_CNT   201728    // int[256]
#define OFF_LIMQ  202752    // uint[256]  (quantized limit, high-16 compare)
#define OFF_SBEST 203776    // ull[256] = 2048
#define OFF_MBAR  205824    // 2 x 8B, pad
#define OFF_CAND  205952    // u32[256*CAP] = 24576
#define SMEM_SZ   230528

// ===== kernel 1: norms (bitwise identical math) + emb -> pre-swizzled bf16 =====
__global__ void prep_norms(const float* __restrict__ z, const float* __restrict__ emb) {
    int warp = (blockIdx.x * blockDim.x + threadIdx.x) >> 5;
    int lane = threadIdx.x & 31;
    if (blockIdx.x == 0 && threadIdx.x < 64) g_part[threadIdx.x] = 0.0;
    const float* src; float* dst; bool is_e = false; int er = 0;
    if (warp < N_ROWS) { src = z + (size_t)warp * D_DIM; dst = g_a + warp; }
    else if (warp < N_ROWS + K_CODES) { er = warp - N_ROWS; src = emb + (size_t)er * D_DIM; dst = g_b + er; is_e = true; }
    else return;
    const int chunk = er >> 6, r = er & 63;
    const uint32_t ebase = (uint32_t)chunk * 32768u + (uint32_t)r * 512u;
    float s = 0.f;
#pragma unroll
    for (int i = 0; i < D_DIM / 32; i++) {
        float v = src[lane + i * 32];
        s = __fmaf_rn(v, v, s);
        if (is_e) {
            int j = lane + i * 32;
            uint32_t u = (uint32_t)(j >> 3);
            uint32_t off = ebase + (((u ^ (uint32_t)(r & 7)) << 4) | (uint32_t)((j & 7) * 2));
            *reinterpret_cast<__nv_bfloat16*>(g_eb + off) = __float2bfloat16_rn(v);
        }
    }
#pragma unroll
    for (int o = 16; o > 0; o >>= 1) s = __fadd_rn(s, __shfl_down_sync(0xffffffffu, s, o));
    if (lane == 0) *dst = s;
}

// exact fp32 rescore: identical op sequence to the rel_err=0 scalar kernel
__device__ __noinline__ void rescore(const float* __restrict__ z, const float* __restrict__ emb,
                                     int row, int k,
                                     unsigned long long* __restrict__ sbest) {
    const float* zr = z + (size_t)row * D_DIM;
    const float* er = emb + (size_t)k * D_DIM;
    float c = 0.f;
#pragma unroll 8
    for (int i = 0; i < D_DIM; i += 4) {
        float4 a = *reinterpret_cast<const float4*>(zr + i);
        float4 b = *reinterpret_cast<const float4*>(er + i);
        c = __fmaf_rn(a.x, b.x, c); c = __fmaf_rn(a.y, b.y, c);
        c = __fmaf_rn(a.z, b.z, c); c = __fmaf_rn(a.w, b.w, c);
    }
    float d = __fmaf_rn(-2.0f, c, __fadd_rn(g_a[row], g_b[k]));
    unsigned long long pk = ((unsigned long long)fmap(d) << 32) | (unsigned)k;
    atomicMin(sbest, pk);
}

__global__ void dummy_k() {}

// ===== kernel 2: single-pass bf16 mma.sync GEMM, 16 warps, 1 wave =====
__global__ __launch_bounds__(512, 1)
void gemm_mma(const float* __restrict__ z, const float* __restrict__ emb) {
    extern __shared__ __align__(128) char smem[];
    const uint32_t sbase = s2u(smem);
    const int tid = threadIdx.x;
    const int t = tid & 31;
    const int w = tid >> 5;
    const int warpm = w & 7;          // 8 m-warps: 32 rows each
    const int warpn = w >> 3;         // 2 n-warps: 32 codes each
    const int row0 = blockIdx.x * 256;

    float*    shb  = reinterpret_cast<float*>(smem + OFF_SHB);
    uint32_t* smin = reinterpret_cast<uint32_t*>(smem + OFF_SMIN);
    int*      cnt  = reinterpret_cast<int*>(smem + OFF_CNT);
    uint32_t* limq = reinterpret_cast<uint32_t*>(smem + OFF_LIMQ);
    unsigned long long* sbest = reinterpret_cast<unsigned long long*>(smem + OFF_SBEST);
    uint32_t* cand = reinterpret_cast<uint32_t*>(smem + OFF_CAND);
    const uint32_t mbar0 = sbase + OFF_MBAR, mbar1 = sbase + OFF_MBAR + 8;

    if (tid < 256) { smin[tid] = 0xFF800000u; cnt[tid] = 0; sbest[tid] = ~0ull; }
    for (int i = tid; i < K_CODES; i += 512) shb[i] = g_b[i];
    if (tid == 0) { MB_INIT(mbar0, 1); MB_INIT(mbar1, 1); }
    __syncthreads();

    // kick off B chunks 0 and 1 (g_eb is pre-swizzled, 32KB per chunk)
    if (tid == 0) {
        MB_EXPECT(mbar0, 32768);
        BULK_G2S(sbase + OFF_B, (const void*)(g_eb), 32768, mbar0);
        MB_EXPECT(mbar1, 32768);
        BULK_G2S(sbase + OFF_B + 32768, (const void*)(g_eb + 32768), 32768, mbar1);
    }

    // A: 256 rows x 256 bf16 (fp32 -> bf16), 512B pitch, unit-xor swizzle
    for (int i = tid; i < 256 * 32; i += 512) {
        int r = i >> 5, u = i & 31;
        const float4* s4 = reinterpret_cast<const float4*>(z + (size_t)(row0 + r) * D_DIM + u * 8);
        float4 f0 = s4[0], f1 = s4[1];
        uint4 v = { pbf2(f0.x, f0.y), pbf2(f0.z, f0.w), pbf2(f1.x, f1.y), pbf2(f1.z, f1.w) };
        *reinterpret_cast<uint4*>(smem + OFF_A + r * 512 + ((u ^ (r & 7)) << 4)) = v;
    }
    __syncthreads();

    // ldmatrix lane addressing
    const int t7 = t & 7;
    const int arow = t7 + ((t >> 3) & 1) * 8;
    const int asel = (t >> 4) & 1;
    const int brow = t7 + ((t >> 4) & 1) * 8;
    const int bsel = (t >> 3) & 1;
    const uint32_t abase = sbase + OFF_A + (uint32_t)(warpm * 32 + arow) * 512;
    const int n0 = warpn * 32;
    const int crow = t >> 2;
    const int ccol = 2 * (t & 3);

    for (int c = 0; c < 16; c++) {
        const int b = c & 1;
        const int c0 = c * 64;
        const uint32_t mb = b ? mbar1 : mbar0;
        const uint32_t bbase = sbase + OFF_B + (uint32_t)(b * 32768 + (warpn * 32 + brow) * 512);

        MB_WAIT(mb, (c >> 1) & 1);

        float acc[2][4][4];
#pragma unroll
        for (int im = 0; im < 2; im++)
#pragma unroll
            for (int in = 0; in < 4; in++)
#pragma unroll
                for (int r = 0; r < 4; r++) acc[im][in][r] = 0.f;

#pragma unroll
        for (int ks = 0; ks < 16; ks++) {
            uint32_t ua = (uint32_t)(((2 * ks + asel) ^ t7) << 4);
            uint32_t ub = (uint32_t)(((2 * ks + bsel) ^ t7) << 4);
            uint32_t af[2][4], bf[2][4];
            LDSM4(af[0], abase + ua);
            LDSM4(af[1], abase + 8192 + ua);
            LDSM4(bf[0], bbase + ub);
            LDSM4(bf[1], bbase + 8192 + ub);
#pragma unroll
            for (int im = 0; im < 2; im++) {
                MMA16816(acc[im][0], af[im], bf[0][0], bf[0][1]);
                MMA16816(acc[im][1], af[im], bf[0][2], bf[0][3]);
                MMA16816(acc[im][2], af[im], bf[1][0], bf[1][1]);
                MMA16816(acc[im][3], af[im], bf[1][2], bf[1][3]);
            }
        }

        // ---- epilogue phase 1: per-row running min ----
#pragma unroll
        for (int im = 0; im < 2; im++) {
#pragma unroll
            for (int h = 0; h < 2; h++) {
                const int row = warpm * 32 + im * 16 + crow + h * 8;
                float mn = CUDART_INF_F;
#pragma unroll
                for (int in = 0; in < 4; in++) {
                    int nl = n0 + in * 8 + ccol;
                    mn = fminf(mn, __fmaf_rn(-2.0f, acc[im][in][2 * h],     shb[c0 + nl]));
                    mn = fminf(mn, __fmaf_rn(-2.0f, acc[im][in][2 * h + 1], shb[c0 + nl + 1]));
                }
                mn = fminf(mn, __shfl_xor_sync(0xffffffffu, mn, 1));
                mn = fminf(mn, __shfl_xor_sync(0xffffffffu, mn, 2));
                if ((t & 3) == 0) atomicMin(&smin[row], fmap(mn));
            }
        }
        __syncthreads();   // smin includes all of chunk c; B buffer b is free now

        // issue bulk copy for chunk c+2 (overlaps phase 2 + next chunk's MMA)
        if (c < 14 && tid == 0) {
            MB_EXPECT(mb, 32768);
            BULK_G2S(sbase + OFF_B + b * 32768,
                     (const void*)(g_eb + (size_t)(c + 2) * 32768), 32768, mb);
        }

        // ---- epilogue phase 2: tight-limit candidate collection ----
        // (smin may shrink concurrently from faster warps; limits only get
        //  tighter and never drop below the final limit -> still a superset)
#pragma unroll
        for (int im = 0; im < 2; im++) {
#pragma unroll
            for (int h = 0; h < 2; h++) {
                const int row = warpm * 32 + im * 16 + crow + h * 8;
                const float lim = funmap(smin[row]) + MARGIN;
#pragma unroll
                for (int in = 0; in < 4; in++) {
#pragma unroll
                    for (int p = 0; p < 2; p++) {
                        int nl = n0 + in * 8 + ccol + p;
                        float s = __fmaf_rn(-2.0f, acc[im][in][2 * h + p], shb[c0 + nl]);
                        if (s <= lim) {
                            int idx = atomicAdd(&cnt[row], 1);
                            if (idx < CAP)
                                cand[row * CAP + idx] =
                                    (fmap(s) & 0xFFFF0000u) | (unsigned)(c0 + nl);
                        }
                    }
                }
            }
        }
        // no second sync: next chunk begins with its own MB_WAIT
    }
    __syncthreads();

    // ---- final quantized limits, filter, exact rescore ----
    if (tid < 256) limq[tid] = fmap(funmap(smin[tid]) + MARGIN) >> 16;
    __syncthreads();

    for (int i = tid; i < 256 * CAP; i += 512) {
        int row = i / CAP, slot = i % CAP;
        int ne = min(cnt[row], CAP);
        if (slot < ne) {
            uint32_t pk = cand[row * CAP + slot];
            if ((pk >> 16) <= limq[row])      // conservative (truncated) filter
                rescore(z, emb, row0 + row, (int)(pk & 0x3FFu), &sbest[row]);
        }
    }
    for (int row = w; row < 256; row += 16) {        // overflow fallback (now ~never)
        if (cnt[row] > CAP)
            for (int k = t; k < K_CODES; k += 32)
                rescore(z, emb, row0 + row, k, &sbest[row]);
    }
    __syncthreads();

    if (tid < 256) g_idx[row0 + tid] = (int)(unsigned)(sbest[tid] & 0xFFFFFFFFull);
}

// ===== kernel 3: gather + straight-through output + MSE partials =====
__global__ void finalize_out(const float* __restrict__ z, const float* __restrict__ emb,
                             float* __restrict__ out) {
    int tt = blockIdx.x * 256 + threadIdx.x;
    int base = tt * 4, n = base >> 8, d0 = base & 255;
    int code = g_idx[n];
    float4 q  = *reinterpret_cast<const float4*>(&emb[(size_t)code * D_DIM + d0]);
    float4 zv = *reinterpret_cast<const float4*>(&z[(size_t)base]);
    float dx = __fadd_rn(q.x, -zv.x), dy = __fadd_rn(q.y, -zv.y);
    float dz = __fadd_rn(q.z, -zv.z), dw = __fadd_rn(q.w, -zv.w);
    float4 ov = { __fadd_rn(zv.x, dx), __fadd_rn(zv.y, dy), __fadd_rn(zv.z, dz), __fadd_rn(zv.w, dw) };
    *reinterpret_cast<float4*>(&out[(size_t)base]) = ov;

    double s = (double)dx * dx + (double)dy * dy + (double)dz * dz + (double)dw * dw;
#pragma unroll
    for (int o = 16; o > 0; o >>= 1) s += __shfl_down_sync(0xffffffffu, s, o);
    __shared__ double ws[8];
    int lane = threadIdx.x & 31, wid = threadIdx.x >> 5;
    if (lane == 0) ws[wid] = s;
    __syncthreads();
    if (threadIdx.x == 0) {
        double bs = 0.0;
#pragma unroll
        for (int ww = 0; ww < 8; ww++) bs += ws[ww];
        atomicAdd(&g_part[blockIdx.x & 63], bs);
    }
}

__global__ void loss_final(float* __restrict__ out, int out_size) {
    int lane = threadIdx.x;                      // 64 threads
    double s = (lane < 64) ? g_part[lane] : 0.0;
#pragma unroll
    for (int o = 16; o > 0; o >>= 1) s += __shfl_down_sync(0xffffffffu, s, o);
    __shared__ double w2[2];
    if ((lane & 31) == 0) w2[lane >> 5] = s;
    __syncthreads();
    if (lane == 0) {
        double tot = w2[0] + w2[1];
        float mf = (float)(tot / (double)((size_t)N_ROWS * D_DIM));
        out[out_size - 1] = __fadd_rn(mf, __fmul_rn(0.25f, mf));
    }
}

extern "C" void kernel_launch(void* const* d_in, const int* in_sizes, int n_in,
                              void* d_out, int out_size) {
    const float* z   = (const float*)d_in[0];
    const float* emb = (const float*)d_in[1];
    float* out = (float*)d_out;

    cudaFuncSetAttribute(gemm_mma, cudaFuncAttributeMaxDynamicSharedMemorySize, SMEM_SZ);

    prep_norms<<<(N_ROWS + K_CODES) / 8, 256>>>(z, emb);
    dummy_k<<<1, 32>>>();      // launch-index padding so ncu (-s 5 -c 1)
    dummy_k<<<1, 32>>>();      // lands on gemm_mma
    gemm_mma<<<N_ROWS / 256, 512, SMEM_SZ>>>(z, emb);
    finalize_out<<<(N_ROWS * D_DIM) / (256 * 4), 256>>>(z, emb, out);
    loss_final<<<1, 64>>>(out, out_size);
}